// round 6
// baseline (speedup 1.0000x reference)
#include <cuda_runtime.h>
#include <math.h>

#define BN 32     // B*C images
#define HH 256
#define WW 256
#define TILE 16   // output rows per block
#define HALO 8    // shared halo rows each side; covers column d <= 8 exactly
#define SROWS (TILE + 2*HALO)   // 32
#define FG_INF 1e6f
#define BIGF   3.0e38f          // padding: r2 + BIGF never wins, no overflow

// exact per-pixel row distance recompute from x (cold path, never hot)
__device__ __forceinline__ float row_g_global(const float* __restrict__ xrow, int j) {
    if (xrow[j] == 0.0f) return 0.0f;
    int dl = 1 << 30, dr = 1 << 30;
    for (int t = j - 1; t >= 0; --t) if (xrow[t] == 0.0f) { dl = j - t; break; }
    for (int t = j + 1; t < WW; ++t) if (xrow[t] == 0.0f) { dr = t - j; break; }
    int d = min(dl, dr);
    if (d >= (1 << 30)) return FG_INF + fminf((float)(j + 1), (float)(WW - j));
    return (float)d;
}

__global__ void __launch_bounds__(512, 4)
edt_fused(const float* __restrict__ x, float* __restrict__ out) {
    __shared__ float g2s[SROWS][WW];   // 32 KB; sign bit = "input was NaN"

    const int n  = blockIdx.y;                 // image
    const int i0 = blockIdx.x * TILE;          // first output row
    const int rowbase = i0 - HALO;             // global row of shared row 0
    const int b    = threadIdx.x & 31;         // lane: owns pixels 8b..8b+7
    const int wrp  = threadIdx.x >> 5;         // 0..15

    // ---- Phase 1: row distances (warp-per-row, float4 + shuffle-composed mask) ----
    #pragma unroll
    for (int pass = 0; pass < 2; ++pass) {
        const int lr = wrp + pass * 16;        // local shared row 0..31
        const int gr = rowbase + lr;           // global row
        float4* srow4 = reinterpret_cast<float4*>(&g2s[lr][8 * b]);
        if (gr < 0 || gr >= HH) {
            const float4 big = make_float4(BIGF, BIGF, BIGF, BIGF);
            srow4[0] = big;
            srow4[1] = big;
            continue;
        }
        const float* __restrict__ xr = x + (n * HH + gr) * WW;
        const float4 x0 = reinterpret_cast<const float4*>(xr)[2 * b];
        const float4 x1 = reinterpret_cast<const float4*>(xr)[2 * b + 1];

        // local 8-bit bg / NaN masks for pixels 8b..8b+7
        unsigned m8 =  (unsigned)(x0.x == 0.0f)        | ((unsigned)(x0.y == 0.0f) << 1)
                    | ((unsigned)(x0.z == 0.0f) << 2)  | ((unsigned)(x0.w == 0.0f) << 3)
                    | ((unsigned)(x1.x == 0.0f) << 4)  | ((unsigned)(x1.y == 0.0f) << 5)
                    | ((unsigned)(x1.z == 0.0f) << 6)  | ((unsigned)(x1.w == 0.0f) << 7);
        unsigned nn8 = (unsigned)isnan(x0.x)        | ((unsigned)isnan(x0.y) << 1)
                    | ((unsigned)isnan(x0.z) << 2)  | ((unsigned)isnan(x0.w) << 3)
                    | ((unsigned)isnan(x1.x) << 4)  | ((unsigned)isnan(x1.y) << 5)
                    | ((unsigned)isnan(x1.z) << 6)  | ((unsigned)isnan(x1.w) << 7);

        // compose 32-bit word q = b>>2 (pixels 32q..32q+31) within each lane quad
        unsigned w = m8 << (8 * (b & 3));
        w |= __shfl_xor_sync(0xFFFFFFFFu, w, 1);
        w |= __shfl_xor_sync(0xFFFFFFFFu, w, 2);
        // neighbor words
        unsigned wm = __shfl_sync(0xFFFFFFFFu, w, (b - 4) & 31);
        unsigned wp = __shfl_sync(0xFFFFFFFFu, w, (b + 4) & 31);
        if (b < 4)  wm = 0u;
        if (b >= 28) wp = 0u;

        float s2v[8];
        #pragma unroll
        for (int t = 0; t < 8; ++t) {
            const int pb = 8 * (b & 3) + t;    // bit position within word w
            float s2;
            if ((m8 >> t) & 1u) {
                s2 = 0.0f;
            } else {
                // windows of 32 pixels each side, one funnel shift each
                const unsigned R = __funnelshift_rc(w, wp, pb + 1);
                const unsigned L = __funnelshift_lc(wm, w, 32 - pb);
                const int dr = R ? __ffs(R) : 1000;
                const int dl = L ? (__clz(L) + 1) : 1000;
                const int d = min(dr, dl);
                if (d < 1000) {
                    s2 = (float)(d * d);
                } else {
                    const float g = row_g_global(xr, 8 * b + t);  // exact cold path
                    s2 = g * g;
                }
                if ((nn8 >> t) & 1u) s2 = -s2;  // fg => g>=1, sign bit free
            }
            s2v[t] = s2;
        }
        srow4[0] = make_float4(s2v[0], s2v[1], s2v[2], s2v[3]);
        srow4[1] = make_float4(s2v[4], s2v[5], s2v[6], s2v[7]);
    }
    __syncthreads();

    // ---- Phase 2: column lower-envelope (exact early exit) ----
    const int j   = threadIdx.x & (WW - 1);
    const int lo0 = (threadIdx.x >> 8) * 8;    // first of 8 local output rows

    float v[16];                               // shared rows HALO+lo0-4 .. +11
    #pragma unroll
    for (int t = 0; t < 16; ++t)
        v[t] = g2s[HALO + lo0 - 4 + t][j];

    #pragma unroll
    for (int p = 0; p < 8; ++p) {
        const int c = 4 + p;
        const float center = v[c];
        const bool nanp = signbit(center);
        float best = fabsf(center);
        #pragma unroll
        for (int r = 1; r <= 4; ++r) {
            const float r2 = (float)(r * r);
            best = fminf(best, r2 + fabsf(v[c - r]));
            best = fminf(best, r2 + fabsf(v[c + r]));
        }
        if (25.0f < best) {
            const int s = HALO + lo0 + p;      // this pixel's shared row
            #pragma unroll
            for (int r = 5; r <= HALO; ++r) {
                const float r2 = (float)(r * r);
                if (r2 >= best) break;
                best = fminf(best, r2 + fabsf(g2s[s - r][j]));
                best = fminf(best, r2 + fabsf(g2s[s + r][j]));
            }
            // exact global fallback (never taken for this distribution)
            if ((float)(HALO * HALO) < best) {
                const int i = i0 + lo0 + p;
                for (int r = HALO + 1; r < HH; ++r) {
                    const float r2 = (float)(r * r);
                    if (r2 >= best) break;
                    const int up = i - r, dn = i + r;
                    if (up >= 0) {
                        const float g = row_g_global(x + (n * HH + up) * WW, j);
                        best = fminf(best, r2 + g * g);
                    }
                    if (dn < HH) {
                        const float g = row_g_global(x + (n * HH + dn) * WW, j);
                        best = fminf(best, r2 + g * g);
                    }
                }
            }
        }
        const float d = sqrtf(best);
        out[(n * HH + i0 + lo0 + p) * WW + j] =
            nanp ? __int_as_float(0x7FC00000) : d;
    }
}

extern "C" void kernel_launch(void* const* d_in, const int* in_sizes, int n_in,
                              void* d_out, int out_size) {
    const float* x = (const float*)d_in[0];
    float* out = (float*)d_out;
    edt_fused<<<dim3(HH / TILE, BN), 512>>>(x, out);
}

// round 7
// speedup vs baseline: 1.0284x; 1.0284x over previous
#include <cuda_runtime.h>
#include <math.h>

#define BN 32     // B*C images
#define HH 256
#define WW 256
#define TILE 16   // output rows per block
#define HALO 8    // shared halo rows each side; covers column d <= 8 exactly
#define SROWS (TILE + 2*HALO)   // 32
#define FG_INF 1e6f
#define BIGF   3.0e38f          // padding: r2 + BIGF never wins, no overflow

// exact per-pixel row distance recompute from x (cold path, never hot)
__device__ __forceinline__ float row_g_global(const float* __restrict__ xrow, int j) {
    if (xrow[j] == 0.0f) return 0.0f;
    int dl = 1 << 30, dr = 1 << 30;
    for (int t = j - 1; t >= 0; --t) if (xrow[t] == 0.0f) { dl = j - t; break; }
    for (int t = j + 1; t < WW; ++t) if (xrow[t] == 0.0f) { dr = t - j; break; }
    int d = min(dl, dr);
    if (d >= (1 << 30)) return FG_INF + fminf((float)(j + 1), (float)(WW - j));
    return (float)d;
}

__global__ void __launch_bounds__(512, 4)
edt_fused(const float* __restrict__ x, float* __restrict__ out) {
    __shared__ float g2s[SROWS][WW];   // 32 KB; sign bit = "input was NaN"

    const int n  = blockIdx.y;                 // image
    const int i0 = blockIdx.x * TILE;          // first output row
    const int rowbase = i0 - HALO;             // global row of shared row 0
    const int b    = threadIdx.x & 31;         // lane
    const int wrp  = threadIdx.x >> 5;         // 0..15

    // ------- Phase 1: row distances (warp-per-row, funnel-shift search) -------
    #pragma unroll
    for (int pass = 0; pass < 2; ++pass) {
        const int lr = wrp + pass * 16;        // local shared row 0..31
        const int gr = rowbase + lr;           // global row
        if (gr < 0 || gr >= HH) {
            #pragma unroll
            for (int k = 0; k < 8; ++k) g2s[lr][b + 32 * k] = BIGF;
            continue;
        }
        const float* __restrict__ xr = x + (n * HH + gr) * WW;

        unsigned mm[10];                       // bg mask words, zero-padded ends
        unsigned nn8 = 0u;                     // bit k = isnan(pixel b+32k)
        mm[0] = 0u; mm[9] = 0u;
        #pragma unroll
        for (int k = 0; k < 8; ++k) {
            const float xv = xr[b + 32 * k];
            mm[k + 1] = __ballot_sync(0xFFFFFFFFu, xv == 0.0f);  // NaN -> fg
            nn8 |= ((unsigned)isnan(xv)) << k;
        }

        #pragma unroll
        for (int k = 0; k < 8; ++k) {
            const int j = b + 32 * k;
            float s2;
            if ((mm[k + 1] >> b) & 1u) {
                s2 = 0.0f;
            } else {
                // 32-bit windows on each side, one funnel shift each:
                // R bit t  = pixel j+1+t ;  L bit (31-t) = pixel j-1-t
                const unsigned R = __funnelshift_rc(mm[k + 1], mm[k + 2], b + 1);
                const unsigned L = __funnelshift_lc(mm[k], mm[k + 1], 32 - b);
                const int dr = R ? __ffs(R) : 1000;
                const int dl = L ? (__clz(L) + 1) : 1000;
                const int d = min(dr, dl);
                if (d < 1000) {
                    s2 = (float)(d * d);
                } else {
                    const float g = row_g_global(xr, j);   // exact cold path
                    s2 = g * g;
                }
                if ((nn8 >> k) & 1u) s2 = -s2;  // fg => g>=1, sign bit free
            }
            g2s[lr][j] = s2;
        }
    }
    __syncthreads();

    // ------- Phase 2: column lower-envelope (exact early exit) -------
    const int j   = threadIdx.x & (WW - 1);
    const int lo0 = (threadIdx.x >> 8) * 8;    // first of 8 local output rows

    float v[16];                               // shared rows HALO+lo0-4 .. +11
    #pragma unroll
    for (int t = 0; t < 16; ++t)
        v[t] = g2s[HALO + lo0 - 4 + t][j];

    #pragma unroll
    for (int p = 0; p < 8; ++p) {
        const int c = 4 + p;
        const float center = v[c];
        const bool nanp = signbit(center);
        float best = fabsf(center);
        #pragma unroll
        for (int r = 1; r <= 4; ++r) {
            const float r2 = (float)(r * r);
            best = fminf(best, r2 + fabsf(v[c - r]));
            best = fminf(best, r2 + fabsf(v[c + r]));
        }
        if (25.0f < best) {
            const int s = HALO + lo0 + p;      // this pixel's shared row
            #pragma unroll
            for (int r = 5; r <= HALO; ++r) {
                const float r2 = (float)(r * r);
                if (r2 >= best) break;
                best = fminf(best, r2 + fabsf(g2s[s - r][j]));
                best = fminf(best, r2 + fabsf(g2s[s + r][j]));
            }
            // exact global fallback (never taken for this distribution)
            if ((float)(HALO * HALO) < best) {
                const int i = i0 + lo0 + p;
                for (int r = HALO + 1; r < HH; ++r) {
                    const float r2 = (float)(r * r);
                    if (r2 >= best) break;
                    const int up = i - r, dn = i + r;
                    if (up >= 0) {
                        const float g = row_g_global(x + (n * HH + up) * WW, j);
                        best = fminf(best, r2 + g * g);
                    }
                    if (dn < HH) {
                        const float g = row_g_global(x + (n * HH + dn) * WW, j);
                        best = fminf(best, r2 + g * g);
                    }
                }
            }
        }
        const float d = sqrtf(best);
        out[(n * HH + i0 + lo0 + p) * WW + j] =
            nanp ? __int_as_float(0x7FC00000) : d;
    }
}

extern "C" void kernel_launch(void* const* d_in, const int* in_sizes, int n_in,
                              void* d_out, int out_size) {
    const float* x = (const float*)d_in[0];
    float* out = (float*)d_out;
    edt_fused<<<dim3(HH / TILE, BN), 512>>>(x, out);
}

// round 8
// speedup vs baseline: 1.1749x; 1.1425x over previous
#include <cuda_runtime.h>
#include <math.h>

#define BN 32     // B*C images
#define HH 256
#define WW 256
#define TILE 32   // output rows per block
#define HALO 8    // shared halo rows each side; covers column d <= 8 exactly
#define SROWS (TILE + 2*HALO)   // 48
#define FG_INF 1e6f
#define BIGF   3.0e38f          // padding: r2 + BIGF never wins, no overflow

// exact per-pixel row distance recompute from x (cold path, never hot)
__device__ __forceinline__ float row_g_global(const float* __restrict__ xrow, int j) {
    if (xrow[j] == 0.0f) return 0.0f;
    int dl = 1 << 30, dr = 1 << 30;
    for (int t = j - 1; t >= 0; --t) if (xrow[t] == 0.0f) { dl = j - t; break; }
    for (int t = j + 1; t < WW; ++t) if (xrow[t] == 0.0f) { dr = t - j; break; }
    int d = min(dl, dr);
    if (d >= (1 << 30)) return FG_INF + fminf((float)(j + 1), (float)(WW - j));
    return (float)d;
}

__global__ void __launch_bounds__(512, 3)
edt_fused(const float* __restrict__ x, float* __restrict__ out) {
    __shared__ float g2s[SROWS][WW];   // 48 KB; sign bit = "input was NaN"

    const int n  = blockIdx.y;                 // image
    const int i0 = blockIdx.x * TILE;          // first output row
    const int rowbase = i0 - HALO;             // global row of shared row 0
    const int b    = threadIdx.x & 31;         // lane
    const int wrp  = threadIdx.x >> 5;         // 0..15

    // ------- Phase 1: row distances (warp-per-row, funnel-shift search) -------
    #pragma unroll
    for (int pass = 0; pass < 3; ++pass) {
        const int lr = wrp + pass * 16;        // local shared row 0..47
        const int gr = rowbase + lr;           // global row
        if (gr < 0 || gr >= HH) {
            #pragma unroll
            for (int k = 0; k < 8; ++k) g2s[lr][b + 32 * k] = BIGF;
            continue;
        }
        const float* __restrict__ xr = x + (n * HH + gr) * WW;

        unsigned mm[10];                       // bg mask words, zero-padded ends
        unsigned nn8 = 0u;                     // bit k = isnan(pixel b+32k)
        mm[0] = 0u; mm[9] = 0u;
        #pragma unroll
        for (int k = 0; k < 8; ++k) {
            const float xv = xr[b + 32 * k];
            mm[k + 1] = __ballot_sync(0xFFFFFFFFu, xv == 0.0f);  // NaN -> fg
            nn8 |= ((unsigned)isnan(xv)) << k;
        }

        #pragma unroll
        for (int k = 0; k < 8; ++k) {
            const int j = b + 32 * k;
            float s2;
            if ((mm[k + 1] >> b) & 1u) {
                s2 = 0.0f;
            } else {
                // 32-bit windows on each side, one funnel shift each:
                // R bit t  = pixel j+1+t ;  L bit (31-t) = pixel j-1-t
                const unsigned R = __funnelshift_rc(mm[k + 1], mm[k + 2], b + 1);
                const unsigned L = __funnelshift_lc(mm[k], mm[k + 1], 32 - b);
                const int dr = R ? __ffs(R) : 1000;
                const int dl = L ? (__clz(L) + 1) : 1000;
                const int d = min(dr, dl);
                if (d < 1000) {
                    s2 = (float)(d * d);
                } else {
                    const float g = row_g_global(xr, j);   // exact cold path
                    s2 = g * g;
                }
                if ((nn8 >> k) & 1u) s2 = -s2;  // fg => g>=1, sign bit free
            }
            g2s[lr][j] = s2;
        }
    }
    __syncthreads();

    // ------- Phase 2: column lower-envelope (exact early exit) -------
    const int j    = threadIdx.x & (WW - 1);
    const int half = threadIdx.x >> 8;         // 0..1

    #pragma unroll
    for (int sub = 0; sub < 2; ++sub) {
        const int lo0 = half * 8 + sub * 16;   // 0,8 then 16,24

        float v[16];                           // shared rows HALO+lo0-4 .. +11
        #pragma unroll
        for (int t = 0; t < 16; ++t)
            v[t] = g2s[HALO + lo0 - 4 + t][j];

        #pragma unroll
        for (int p = 0; p < 8; ++p) {
            const int c = 4 + p;
            const float center = v[c];
            const bool nanp = signbit(center);
            float best = fabsf(center);
            #pragma unroll
            for (int r = 1; r <= 4; ++r) {
                const float r2 = (float)(r * r);
                best = fminf(best, r2 + fabsf(v[c - r]));
                best = fminf(best, r2 + fabsf(v[c + r]));
            }
            if (25.0f < best) {
                const int s = HALO + lo0 + p;  // this pixel's shared row
                #pragma unroll
                for (int r = 5; r <= HALO; ++r) {
                    const float r2 = (float)(r * r);
                    if (r2 >= best) break;
                    best = fminf(best, r2 + fabsf(g2s[s - r][j]));
                    best = fminf(best, r2 + fabsf(g2s[s + r][j]));
                }
                // exact global fallback (never taken for this distribution)
                if ((float)(HALO * HALO) < best) {
                    const int i = i0 + lo0 + p;
                    for (int r = HALO + 1; r < HH; ++r) {
                        const float r2 = (float)(r * r);
                        if (r2 >= best) break;
                        const int up = i - r, dn = i + r;
                        if (up >= 0) {
                            const float g = row_g_global(x + (n * HH + up) * WW, j);
                            best = fminf(best, r2 + g * g);
                        }
                        if (dn < HH) {
                            const float g = row_g_global(x + (n * HH + dn) * WW, j);
                            best = fminf(best, r2 + g * g);
                        }
                    }
                }
            }
            const float d = sqrtf(best);
            out[(n * HH + i0 + lo0 + p) * WW + j] =
                nanp ? __int_as_float(0x7FC00000) : d;
        }
    }
}

extern "C" void kernel_launch(void* const* d_in, const int* in_sizes, int n_in,
                              void* d_out, int out_size) {
    const float* x = (const float*)d_in[0];
    float* out = (float*)d_out;
    edt_fused<<<dim3(HH / TILE, BN), 512>>>(x, out);
}

// round 9
// speedup vs baseline: 1.6190x; 1.3780x over previous
#include <cuda_runtime.h>
#include <math.h>

#define BN 32     // B*C images
#define HH 256
#define WW 256
#define TILE 32   // output rows per block
#define HALO 8    // shared halo rows each side; covers column d <= 8 exactly
#define SROWS (TILE + 2*HALO)   // 48
#define FG_INF 1e6f
#define BIGF   3.0e38f          // padding: r2 + BIGF never wins, no overflow

__device__ __forceinline__ float sqrt_approx(float x) {
    float y;
    asm("sqrt.approx.f32 %0, %1;" : "=f"(y) : "f"(x));
    return y;
}

// exact per-pixel row distance recompute from x (cold path, ~never taken)
__device__ __forceinline__ float row_g_global(const float* __restrict__ xrow, int j) {
    if (xrow[j] == 0.0f) return 0.0f;
    int dl = 1 << 30, dr = 1 << 30;
    for (int t = j - 1; t >= 0; --t) if (xrow[t] == 0.0f) { dl = j - t; break; }
    for (int t = j + 1; t < WW; ++t) if (xrow[t] == 0.0f) { dr = t - j; break; }
    int d = min(dl, dr);
    if (d >= (1 << 30)) return FG_INF + fminf((float)(j + 1), (float)(WW - j));
    return (float)d;
}

__global__ void __launch_bounds__(512, 2)
edt_fused(const float* __restrict__ x, float* __restrict__ out) {
    __shared__ float g2s[SROWS][WW];   // 48 KB; sign bit = "input was NaN"

    const int n  = blockIdx.y;                 // image
    const int i0 = blockIdx.x * TILE;          // first output row
    const int rowbase = i0 - HALO;             // global row of shared row 0
    const int b    = threadIdx.x & 31;         // lane
    const int wrp  = threadIdx.x >> 5;         // 0..15

    // --- Phase 1: row distances (warp-per-row, branch-free funnel windows) ---
    #pragma unroll
    for (int pass = 0; pass < 3; ++pass) {
        const int lr = wrp + pass * 16;        // local shared row 0..47
        const int gr = rowbase + lr;           // global row
        if (gr < 0 || gr >= HH) {
            #pragma unroll
            for (int k = 0; k < 8; ++k) g2s[lr][b + 32 * k] = BIGF;
            continue;
        }
        const float* __restrict__ xr = x + (n * HH + gr) * WW;

        unsigned mm[10];                       // bg mask words, zero-padded ends
        unsigned nn8 = 0u;                     // bit k = isnan(pixel b+32k)
        mm[0] = 0u; mm[9] = 0u;
        #pragma unroll
        for (int k = 0; k < 8; ++k) {
            const float xv = xr[b + 32 * k];
            mm[k + 1] = __ballot_sync(0xFFFFFFFFu, xv == 0.0f);  // NaN -> fg
            nn8 |= ((unsigned)isnan(xv)) << k;
        }

        unsigned cold = 0u;
        #pragma unroll
        for (int k = 0; k < 8; ++k) {
            // self-inclusive windows: R bit t = pixel j+t, L bit (31-t) = pixel j-t
            const unsigned R = __funnelshift_rc(mm[k + 1], mm[k + 2], b);
            const unsigned L = __funnelshift_lc(mm[k], mm[k + 1], 31 - b);
            const int dr = R ? (__ffs(R) - 1) : 1000;
            const int dl = L ? __clz(L) : 1000;
            const int d = min(dr, dl);
            cold |= ((unsigned)(d >= 1000)) << k;
            float s2 = (float)(d * d);
            // inject NaN flag into sign bit (fg => d>=1, bg never NaN)
            s2 = __uint_as_float(__float_as_uint(s2) |
                                 (((nn8 >> k) & 1u) << 31));
            g2s[lr][b + 32 * k] = s2;
        }
        if (__any_sync(0xFFFFFFFFu, cold != 0u)) {   // ~never taken
            #pragma unroll 1
            for (int k = 0; k < 8; ++k) if ((cold >> k) & 1u) {
                const int j = b + 32 * k;
                const float g = row_g_global(xr, j);
                float s2 = g * g;
                s2 = __uint_as_float(__float_as_uint(s2) |
                                     (((nn8 >> k) & 1u) << 31));
                g2s[lr][j] = s2;
            }
        }
    }
    __syncthreads();

    // --- Phase 2: column lower-envelope, branch-free r<=3 window, ballot tail ---
    const int j    = threadIdx.x & (WW - 1);
    const int half = threadIdx.x >> 8;         // 0..1

    #pragma unroll
    for (int sub = 0; sub < 2; ++sub) {
        const int lo0 = half * 8 + sub * 16;   // 0,16 / 8,24

        float v[14];                           // shared rows HALO+lo0-3 .. +10
        #pragma unroll
        for (int t = 0; t < 14; ++t)
            v[t] = g2s[HALO + lo0 - 3 + t][j];

        unsigned need = 0u;
        #pragma unroll
        for (int p = 0; p < 8; ++p) {
            const int c = 3 + p;
            const bool nanp = signbit(v[c]);
            float best = fabsf(v[c]);
            #pragma unroll
            for (int r = 1; r <= 3; ++r) {
                const float r2 = (float)(r * r);
                best = fminf(best, r2 + fabsf(v[c - r]));
                best = fminf(best, r2 + fabsf(v[c + r]));
            }
            need |= ((unsigned)(best > 16.0f)) << p;
            const float d = sqrt_approx(best);
            out[(n * HH + i0 + lo0 + p) * WW + j] =
                nanp ? __int_as_float(0x7FC00000) : d;
        }

        // exact tail, warp-uniform and ~never taken (needs d^2 > 16)
        if (__any_sync(0xFFFFFFFFu, need != 0u)) {
            #pragma unroll 1
            for (int p = 0; p < 8; ++p) if ((need >> p) & 1u) {
                const int s = HALO + lo0 + p;  // this pixel's shared row
                const bool nanp = signbit(g2s[s][j]);
                float best = fabsf(g2s[s][j]);
                for (int r = 1; r <= HALO; ++r) {
                    const float r2 = (float)(r * r);
                    if (r2 >= best) break;
                    best = fminf(best, r2 + fabsf(g2s[s - r][j]));
                    best = fminf(best, r2 + fabsf(g2s[s + r][j]));
                }
                if ((float)(HALO * HALO) < best) {
                    const int i = i0 + lo0 + p;
                    for (int r = HALO + 1; r < HH; ++r) {
                        const float r2 = (float)(r * r);
                        if (r2 >= best) break;
                        const int up = i - r, dn = i + r;
                        if (up >= 0) {
                            const float g = row_g_global(x + (n * HH + up) * WW, j);
                            best = fminf(best, r2 + g * g);
                        }
                        if (dn < HH) {
                            const float g = row_g_global(x + (n * HH + dn) * WW, j);
                            best = fminf(best, r2 + g * g);
                        }
                    }
                }
                out[(n * HH + i0 + lo0 + p) * WW + j] =
                    nanp ? __int_as_float(0x7FC00000) : sqrt_approx(best);
            }
        }
    }
}

extern "C" void kernel_launch(void* const* d_in, const int* in_sizes, int n_in,
                              void* d_out, int out_size) {
    const float* x = (const float*)d_in[0];
    float* out = (float*)d_out;
    edt_fused<<<dim3(HH / TILE, BN), 512>>>(x, out);
}